// round 13
// baseline (speedup 1.0000x reference)
#include <cuda_runtime.h>
#include <math.h>

#define N_ANT 64
#define HID   128
#define AP    132   // activation pitch: (4g+tg) bank map -> A-fragment LDS conflict-free
#define WP2   132   // paired-weight pitch in float2 units (== 4 mod 16 -> pair loads conflict-free)
#define SP    68    // score pitch
#define NTH   512

typedef unsigned long long u64;

__device__ __forceinline__ unsigned cvt_tf32(float v) {
    unsigned r; asm("cvt.rna.tf32.f32 %0, %1;" : "=r"(r) : "f"(v)); return r;
}
__device__ __forceinline__ void mma8(float& d0, float& d1, float& d2, float& d3,
                                     unsigned a0, unsigned a1, unsigned a2, unsigned a3,
                                     unsigned b0, unsigned b1) {
    asm("mma.sync.aligned.m16n8k8.row.col.f32.tf32.tf32.f32 "
        "{%0,%1,%2,%3},{%4,%5,%6,%7},{%8,%9},{%0,%1,%2,%3};"
        : "+f"(d0), "+f"(d1), "+f"(d2), "+f"(d3)
        : "r"(a0), "r"(a1), "r"(a2), "r"(a3), "r"(b0), "r"(b1));
}
__device__ __forceinline__ float f4c(const float4& v, int c) {
    return (c == 0) ? v.x : (c == 1) ? v.y : (c == 2) ? v.z : v.w;
}

struct __align__(16) SmemLayout {
    float  B0[N_ANT * AP];
    float  B1[N_ANT * AP];
    float  B2[N_ANT * AP];
    float  B3[N_ANT * AP];
    float2 Ws[64 * WP2];     // paired tf32 weights: [pair-row (<=KDIM/2)][out-col row]
    float  Ss[N_ANT * SP];
    u64    mb[N_ANT];
};

#define EPI_PLAIN  0
#define EPI_RELU   1
#define EPI_SIGADD 2   // C = sigmoid(acc + T)
#define EPI_TANHN  3   // C = tanh(T + R*acc)

// C[64][128] = epi( A[64][KDIM] @ Wg[128][KDIM]^T + bg ), tf32 mma.sync.
// Weights staged coalesced, tf32-rounded once, PRE-PAIRED: Ws[(oct*4+e)*WP2 + row]
// holds (W[row][8oct+e], W[row][8oct+e+4]) -> mainloop B-fragment = one LDS.64.
// NOTE: no trailing barrier — the post-mainloop barrier separates this GEMM's
// Ws/A reads from the next GEMM's staging STS; callers that read C outside a
// following gemm_one must sync first.
template <int KDIM>
__device__ __noinline__ void gemm_one(
    const float* __restrict__ A, const float* __restrict__ Wg,
    const float* __restrict__ bg, float* __restrict__ C,
    const float* __restrict__ T, const float* __restrict__ R,
    float2* __restrict__ Ws, int tid, int mode)
{
    const int lane = tid & 31;
    const int wrp  = tid >> 5;
    const int g    = lane >> 2;
    const int tg   = lane & 3;
    const int mi   = wrp & 3;
    const int ni   = wrp >> 2;
    const int r0   = mi * 16 + g;
    const int r1   = r0 + 8;

    // ---- stage weights as tf32 pairs (coalesced LDG, conflict-free STS.64) ----
    constexpr int NOCT = KDIM / 8;          // octets per weight row (16 or 8)
    constexpr int IT   = (HID * NOCT) / NTH;// octets per thread (4 or 2)
    {
        float4 lo[IT], hi[IT];
#pragma unroll
        for (int i = 0; i < IT; i++) {
            const int f   = tid + i * NTH;
            const int rq  = f / (4 * NOCT);
            const int sfx = f % (4 * NOCT);
            const int row = rq * 4 + ((sfx >> 2) & 3);
            const int oct = ((sfx >> 4) << 2) + (sfx & 3);
            const float* src = Wg + row * KDIM + oct * 8;
            lo[i] = *reinterpret_cast<const float4*>(src);
            hi[i] = *reinterpret_cast<const float4*>(src + 4);
        }
#pragma unroll
        for (int i = 0; i < IT; i++) {
            const int f   = tid + i * NTH;
            const int rq  = f / (4 * NOCT);
            const int sfx = f % (4 * NOCT);
            const int row = rq * 4 + ((sfx >> 2) & 3);
            const int oct = ((sfx >> 4) << 2) + (sfx & 3);
#pragma unroll
            for (int e = 0; e < 4; e++) {
                const int ep = (e + oct) & 3;   // rotation -> conflict-free banks
                const float2 pr = make_float2(
                    __uint_as_float(cvt_tf32(f4c(lo[i], ep))),
                    __uint_as_float(cvt_tf32(f4c(hi[i], ep))));
                Ws[(oct * 4 + ep) * WP2 + row] = pr;
            }
        }
    }

    // D fragments, bias-initialized: cols j = ni*32+nt*8+2tg, j+1; rows r0, r1
    float d[4][4];
#pragma unroll
    for (int nt = 0; nt < 4; nt++) {
        const float2 b2 = *reinterpret_cast<const float2*>(bg + ni * 32 + nt * 8 + 2 * tg);
        d[nt][0] = b2.x; d[nt][1] = b2.y;
        d[nt][2] = b2.x; d[nt][3] = b2.y;
    }

    __syncthreads();   // Ws staged; also orders prior epilogue/attention writes to A

#pragma unroll 4
    for (int ks = 0; ks < KDIM / 8; ks++) {
        const int kk = ks * 8;
        const unsigned a0 = cvt_tf32(A[r0 * AP + kk + tg]);
        const unsigned a1 = cvt_tf32(A[r1 * AP + kk + tg]);
        const unsigned a2 = cvt_tf32(A[r0 * AP + kk + tg + 4]);
        const unsigned a3 = cvt_tf32(A[r1 * AP + kk + tg + 4]);
        const int prow = (ks * 4 + tg) * WP2;
#pragma unroll
        for (int nt = 0; nt < 4; nt++) {
            const int n = ni * 32 + nt * 8 + g;
            const float2 pb = Ws[prow + n];
            mma8(d[nt][0], d[nt][1], d[nt][2], d[nt][3], a0, a1, a2, a3,
                 __float_as_uint(pb.x), __float_as_uint(pb.y));
        }
    }
    __syncthreads();   // all Ws/A reads done -> in-place C safe; next staging safe

#pragma unroll
    for (int nt = 0; nt < 4; nt++) {
        const int j = ni * 32 + nt * 8 + 2 * tg;
        float v0 = d[nt][0], v1 = d[nt][1];
        float v2 = d[nt][2], v3 = d[nt][3];
        if (mode == EPI_RELU) {
            v0 = fmaxf(v0, 0.f); v1 = fmaxf(v1, 0.f);
            v2 = fmaxf(v2, 0.f); v3 = fmaxf(v3, 0.f);
        } else if (mode == EPI_SIGADD) {
            v0 += T[r0 * AP + j]; v1 += T[r0 * AP + j + 1];
            v2 += T[r1 * AP + j]; v3 += T[r1 * AP + j + 1];
            v0 = 1.f / (1.f + __expf(-v0)); v1 = 1.f / (1.f + __expf(-v1));
            v2 = 1.f / (1.f + __expf(-v2)); v3 = 1.f / (1.f + __expf(-v3));
        } else if (mode == EPI_TANHN) {
            v0 = tanhf(T[r0 * AP + j]     + R[r0 * AP + j]     * v0);
            v1 = tanhf(T[r0 * AP + j + 1] + R[r0 * AP + j + 1] * v1);
            v2 = tanhf(T[r1 * AP + j]     + R[r1 * AP + j]     * v2);
            v3 = tanhf(T[r1 * AP + j + 1] + R[r1 * AP + j + 1] * v3);
        }
        *reinterpret_cast<float2*>(C + r0 * AP + j) = make_float2(v0, v1);
        *reinterpret_cast<float2*>(C + r1 * AP + j) = make_float2(v2, v3);
    }
    // no trailing sync (see header comment)
}

// Masked MHA core on tf32 mma. Opens with a barrier: the preceding projection
// epilogues have no trailing sync.
__device__ __noinline__ void attention_mma(
    const float* __restrict__ Q, const float* __restrict__ K,
    const float* __restrict__ V, float* __restrict__ O,
    float* __restrict__ Ss, const u64* __restrict__ mb, int tid)
{
    const float scale = 0.17677669529663687f;  // 1/sqrt(32)
    const int lane = tid & 31;
    const int wrp  = tid >> 5;
    const int g    = lane >> 2;
    const int tg   = lane & 3;
    const int mi   = wrp & 3;
    const int r0   = mi * 16 + g;
    const int r1   = r0 + 8;
    __syncthreads();   // Q/K/V epilogue writes visible
#pragma unroll 1
    for (int h = 0; h < 4; h++) {
        const int c0 = h * 32;
        // ---- scores: S = scale * Q_h @ K_h^T   (M=64, N=64, K=32) ----
        {
            const int nj = wrp >> 2;             // 2 n8-tiles at nj*16
            float sd[2][4] = {{0.f,0.f,0.f,0.f},{0.f,0.f,0.f,0.f}};
#pragma unroll
            for (int ks = 0; ks < 4; ks++) {
                const int kk = c0 + ks * 8;
                const unsigned a0 = cvt_tf32(Q[r0 * AP + kk + tg]);
                const unsigned a1 = cvt_tf32(Q[r1 * AP + kk + tg]);
                const unsigned a2 = cvt_tf32(Q[r0 * AP + kk + tg + 4]);
                const unsigned a3 = cvt_tf32(Q[r1 * AP + kk + tg + 4]);
#pragma unroll
                for (int u = 0; u < 2; u++) {
                    const int n0 = nj * 16 + u * 8;
                    const unsigned b0 = cvt_tf32(K[(n0 + g) * AP + kk + tg]);
                    const unsigned b1 = cvt_tf32(K[(n0 + g) * AP + kk + tg + 4]);
                    mma8(sd[u][0], sd[u][1], sd[u][2], sd[u][3], a0, a1, a2, a3, b0, b1);
                }
            }
#pragma unroll
            for (int u = 0; u < 2; u++) {
                const int n = nj * 16 + u * 8 + 2 * tg;
                Ss[r0 * SP + n]     = sd[u][0] * scale;
                Ss[r0 * SP + n + 1] = sd[u][1] * scale;
                Ss[r1 * SP + n]     = sd[u][2] * scale;
                Ss[r1 * SP + n + 1] = sd[u][3] * scale;
            }
        }
        __syncthreads();
        // ---- masked softmax over keys (8 threads per row) ----
        {
            const int t = tid >> 3;
            const int q = tid & 7;
            const u64 bits = mb[t];
            float mx = -1e30f;
            for (int m = q; m < N_ANT; m += 8)
                if ((bits >> m) & 1ULL) mx = fmaxf(mx, Ss[t * SP + m]);
            mx = fmaxf(mx, __shfl_xor_sync(0xffffffffu, mx, 1));
            mx = fmaxf(mx, __shfl_xor_sync(0xffffffffu, mx, 2));
            mx = fmaxf(mx, __shfl_xor_sync(0xffffffffu, mx, 4));
            float sum = 0.f;
            for (int m = q; m < N_ANT; m += 8) {
                const float p = ((bits >> m) & 1ULL) ? __expf(Ss[t * SP + m] - mx) : 0.f;
                Ss[t * SP + m] = p;
                sum += p;
            }
            sum += __shfl_xor_sync(0xffffffffu, sum, 1);
            sum += __shfl_xor_sync(0xffffffffu, sum, 2);
            sum += __shfl_xor_sync(0xffffffffu, sum, 4);
            const float rinv = 1.f / sum;
            for (int m = q; m < N_ANT; m += 8) Ss[t * SP + m] *= rinv;
        }
        __syncthreads();
        // ---- O[:, c0:c0+32] = P @ V[:, c0:c0+32]   (M=64, N=32, K=64) ----
        {
            const int nt = wrp >> 2;             // 1 n8-tile per warp
            float od[4] = {0.f, 0.f, 0.f, 0.f};
#pragma unroll
            for (int ks = 0; ks < 8; ks++) {
                const int kk = ks * 8;
                const unsigned a0 = cvt_tf32(Ss[r0 * SP + kk + tg]);
                const unsigned a1 = cvt_tf32(Ss[r1 * SP + kk + tg]);
                const unsigned a2 = cvt_tf32(Ss[r0 * SP + kk + tg + 4]);
                const unsigned a3 = cvt_tf32(Ss[r1 * SP + kk + tg + 4]);
                const unsigned b0 = cvt_tf32(V[(kk + tg) * AP + c0 + nt * 8 + g]);
                const unsigned b1 = cvt_tf32(V[(kk + tg + 4) * AP + c0 + nt * 8 + g]);
                mma8(od[0], od[1], od[2], od[3], a0, a1, a2, a3, b0, b1);
            }
            const int j = c0 + nt * 8 + 2 * tg;
            *reinterpret_cast<float2*>(O + r0 * AP + j) = make_float2(od[0], od[1]);
            *reinterpret_cast<float2*>(O + r1 * AP + j) = make_float2(od[2], od[3]);
        }
        __syncthreads();
    }
}

__global__ void __launch_bounds__(NTH, 1) drgn_kernel(
    const float* __restrict__ x, const int* __restrict__ mask,
    const float* __restrict__ hs,
    const float* __restrict__ enc_w, const float* __restrict__ enc_b,
    const float* __restrict__ q1_w, const float* __restrict__ q1_b,
    const float* __restrict__ k1_w, const float* __restrict__ k1_b,
    const float* __restrict__ v1_w, const float* __restrict__ v1_b,
    const float* __restrict__ o1_w, const float* __restrict__ o1_b,
    const float* __restrict__ q2_w, const float* __restrict__ q2_b,
    const float* __restrict__ k2_w, const float* __restrict__ k2_b,
    const float* __restrict__ v2_w, const float* __restrict__ v2_b,
    const float* __restrict__ o2_w, const float* __restrict__ o2_b,
    const float* __restrict__ w_ih, const float* __restrict__ w_hh,
    const float* __restrict__ b_ih, const float* __restrict__ b_hh,
    const float* __restrict__ lin_w, const float* __restrict__ lin_b,
    float* __restrict__ qs_out, float* __restrict__ h3_out, int act)
{
    extern __shared__ char smem_raw[];
    SmemLayout* s = reinterpret_cast<SmemLayout*>(smem_raw);
    const int tid = threadIdx.x;
    const int b   = blockIdx.x;

    // ---- load x tile and mask bitmap (parallel bitmap build: 8 thr/row) ----
    {
        const float* xb = x + (size_t)b * (N_ANT * 64);
        for (int idx = tid; idx < N_ANT * 64; idx += NTH)
            s->B0[(idx >> 6) * AP + (idx & 63)] = xb[idx];

        const int row = tid >> 3;      // 0..63
        const int oq  = tid & 7;       // octet of 8 mask ints
        const int4* mrow = reinterpret_cast<const int4*>(
            mask + ((size_t)b * N_ANT + row) * N_ANT + oq * 8);
        const int4 m0 = mrow[0];
        const int4 m1 = mrow[1];
        unsigned byte =
            (unsigned)(m0.x != 0)        | ((unsigned)(m0.y != 0) << 1) |
            ((unsigned)(m0.z != 0) << 2) | ((unsigned)(m0.w != 0) << 3) |
            ((unsigned)(m1.x != 0) << 4) | ((unsigned)(m1.y != 0) << 5) |
            ((unsigned)(m1.z != 0) << 6) | ((unsigned)(m1.w != 0) << 7);
        u64 part = (u64)byte << (8 * oq);
        part |= __shfl_xor_sync(0xffffffffu, part, 1);
        part |= __shfl_xor_sync(0xffffffffu, part, 2);
        part |= __shfl_xor_sync(0xffffffffu, part, 4);
        if (oq == 0) s->mb[row] = part;
    }
    // (gemm_one's staging __syncthreads orders the fills above before A reads)

    // ---- encoder: xe = relu(x @ enc_w^T) -> B1 ----
    gemm_one<64>(s->B0, enc_w, enc_b, s->B1, nullptr, nullptr, s->Ws, tid, EPI_RELU);

    // ---- MHA layer 1 (input xe in B1) ----
    gemm_one<128>(s->B1, q1_w, q1_b, s->B0, nullptr, nullptr, s->Ws, tid, EPI_RELU);
    gemm_one<128>(s->B1, k1_w, k1_b, s->B2, nullptr, nullptr, s->Ws, tid, EPI_RELU);
    gemm_one<128>(s->B1, v1_w, v1_b, s->B3, nullptr, nullptr, s->Ws, tid, EPI_RELU);
    attention_mma(s->B0, s->B2, s->B3, s->B1, s->Ss, s->mb, tid);
    gemm_one<128>(s->B1, o1_w, o1_b, s->B0, nullptr, nullptr, s->Ws, tid, EPI_RELU);  // h1 -> B0

    // ---- MHA layer 2 (input h1 in B0) ----
    gemm_one<128>(s->B0, q2_w, q2_b, s->B1, nullptr, nullptr, s->Ws, tid, EPI_RELU);
    gemm_one<128>(s->B0, k2_w, k2_b, s->B2, nullptr, nullptr, s->Ws, tid, EPI_RELU);
    gemm_one<128>(s->B0, v2_w, v2_b, s->B3, nullptr, nullptr, s->Ws, tid, EPI_RELU);
    attention_mma(s->B1, s->B2, s->B3, s->B0, s->Ss, s->mb, tid);
    gemm_one<128>(s->B0, o2_w, o2_b, s->B1, nullptr, nullptr, s->Ws, tid, EPI_RELU);  // h2 -> B1

    // ---- load previous hidden state -> B2 ----
    {
        const float* hb = hs + (size_t)b * (N_ANT * HID);
        for (int idx = tid; idx < N_ANT * HID; idx += NTH)
            s->B2[(idx >> 7) * AP + (idx & 127)] = hb[idx];
    }

    // ---- GRU cell: h2 (B1), h (B2) ----
    gemm_one<128>(s->B1, w_ih,             b_ih,       s->B0, nullptr, nullptr, s->Ws, tid, EPI_PLAIN);   // i_r
    gemm_one<128>(s->B1, w_ih + 128 * HID, b_ih + 128, s->B3, nullptr, nullptr, s->Ws, tid, EPI_PLAIN);   // i_z
    gemm_one<128>(s->B1, w_ih + 256 * HID, b_ih + 256, s->B1, nullptr, nullptr, s->Ws, tid, EPI_PLAIN);   // i_n (in place)
    gemm_one<128>(s->B2, w_hh,             b_hh,       s->B0, s->B0,  nullptr,  s->Ws, tid, EPI_SIGADD);  // r
    gemm_one<128>(s->B2, w_hh + 128 * HID, b_hh + 128, s->B3, s->B3,  nullptr,  s->Ws, tid, EPI_SIGADD);  // z
    gemm_one<128>(s->B2, w_hh + 256 * HID, b_hh + 256, s->B1, s->B1,  s->B0,    s->Ws, tid, EPI_TANHN);   // n

    __syncthreads();   // z/n epilogue writes visible before the combine

    // ---- h3 = (1-z)*n + z*h ; write h3 to gmem and keep in B1 ----
    {
        float* h3b = h3_out + (size_t)b * (N_ANT * HID);
        for (int idx = tid; idx < N_ANT * HID; idx += NTH) {
            const int off = (idx >> 7) * AP + (idx & 127);
            const float z  = s->B3[off];
            const float h3 = (1.f - z) * s->B1[off] + z * s->B2[off];
            s->B1[off] = h3;
            h3b[idx]   = h3;
        }
    }
    __syncthreads();

    // ---- qs = h3 @ lin_w^T + lin_b ----
    {
        float* qb = qs_out + (size_t)b * (N_ANT * act);
        for (int idx = tid; idx < N_ANT * act; idx += NTH) {
            const int t = idx / act;
            const int a = idx - t * act;
            const float* wr = lin_w + a * HID;
            const float* hr = s->B1 + t * AP;
            float sacc = lin_b[a];
#pragma unroll 8
            for (int k = 0; k < HID; k += 4) {
                const float4 h4 = *reinterpret_cast<const float4*>(hr + k);
                const float4 w4 = *reinterpret_cast<const float4*>(wr + k);
                sacc = fmaf(h4.x, w4.x, sacc);
                sacc = fmaf(h4.y, w4.y, sacc);
                sacc = fmaf(h4.z, w4.z, sacc);
                sacc = fmaf(h4.w, w4.w, sacc);
            }
            qb[idx] = sacc;
        }
    }
}

extern "C" void kernel_launch(void* const* d_in, const int* in_sizes, int n_in,
                              void* d_out, int out_size)
{
    const float* x     = (const float*)d_in[0];
    const int*   mask  = (const int*)  d_in[1];
    const float* hs    = (const float*)d_in[2];
    const float* enc_w = (const float*)d_in[3];
    const float* enc_b = (const float*)d_in[4];
    const float* q1_w  = (const float*)d_in[5];
    const float* q1_b  = (const float*)d_in[6];
    const float* k1_w  = (const float*)d_in[7];
    const float* k1_b  = (const float*)d_in[8];
    const float* v1_w  = (const float*)d_in[9];
    const float* v1_b  = (const float*)d_in[10];
    const float* o1_w  = (const float*)d_in[11];
    const float* o1_b  = (const float*)d_in[12];
    const float* q2_w  = (const float*)d_in[13];
    const float* q2_b  = (const float*)d_in[14];
    const float* k2_w  = (const float*)d_in[15];
    const float* k2_b  = (const float*)d_in[16];
    const float* v2_w  = (const float*)d_in[17];
    const float* v2_b  = (const float*)d_in[18];
    const float* o2_w  = (const float*)d_in[19];
    const float* o2_b  = (const float*)d_in[20];
    const float* w_ih  = (const float*)d_in[21];
    const float* w_hh  = (const float*)d_in[22];
    const float* b_ih  = (const float*)d_in[23];
    const float* b_hh  = (const float*)d_in[24];
    const float* lin_w = (const float*)d_in[25];
    const float* lin_b = (const float*)d_in[26];

    const int bs  = in_sizes[0] / (N_ANT * 64);
    const int act = in_sizes[25] / HID;  // 20

    float* qs = (float*)d_out;
    float* h3 = qs + (size_t)bs * N_ANT * act;

    const int smem_bytes = (int)sizeof(SmemLayout);
    cudaFuncSetAttribute(drgn_kernel, cudaFuncAttributeMaxDynamicSharedMemorySize, smem_bytes);

    drgn_kernel<<<bs, NTH, smem_bytes>>>(
        x, mask, hs, enc_w, enc_b,
        q1_w, q1_b, k1_w, k1_b, v1_w, v1_b, o1_w, o1_b,
        q2_w, q2_b, k2_w, k2_b, v2_w, v2_b, o2_w, o2_b,
        w_ih, w_hh, b_ih, b_hh, lin_w, lin_b,
        qs, h3, act);
}

// round 14
// speedup vs baseline: 1.4079x; 1.4079x over previous
#include <cuda_runtime.h>
#include <math.h>

#define N_ANT 64
#define HID   128
#define AP    132   // activation pitch: (4g+tg) bank map -> A-fragment LDS conflict-free
#define WPF   132   // full-weight pitch: B-fragment loads conflict-free
#define SP    68    // score pitch
#define NTH   512

typedef unsigned long long u64;

__device__ __forceinline__ unsigned cvt_tf32(float v) {
    unsigned r; asm("cvt.rna.tf32.f32 %0, %1;" : "=r"(r) : "f"(v)); return r;
}
__device__ __forceinline__ void mma8(float& d0, float& d1, float& d2, float& d3,
                                     unsigned a0, unsigned a1, unsigned a2, unsigned a3,
                                     unsigned b0, unsigned b1) {
    asm("mma.sync.aligned.m16n8k8.row.col.f32.tf32.tf32.f32 "
        "{%0,%1,%2,%3},{%4,%5,%6,%7},{%8,%9},{%0,%1,%2,%3};"
        : "+f"(d0), "+f"(d1), "+f"(d2), "+f"(d3)
        : "r"(a0), "r"(a1), "r"(a2), "r"(a3), "r"(b0), "r"(b1));
}

struct __align__(16) SmemLayout {
    float B0[N_ANT * AP];
    float B1[N_ANT * AP];
    float B2[N_ANT * AP];
    float B3[N_ANT * AP];
    float Ws[HID * WPF];     // one full weight matrix, tf32-rounded at staging
    float Ss[N_ANT * SP];
    u64   mb[N_ANT];
};

#define EPI_PLAIN  0
#define EPI_RELU   1
#define EPI_SIGADD 2   // C = sigmoid(acc + T)
#define EPI_TANHN  3   // C = tanh(T + R*acc)

// ---- weight movement: coalesced LDG into registers / tf32-rounded STS ----
template <int KDIM>
__device__ __forceinline__ void ldg_w(const float* __restrict__ Wg, int tid, float4* r) {
    constexpr int C4 = KDIM / 4;
    constexpr int IT = (HID * C4) / NTH;   // 8 (K=128) or 4 (K=64)
#pragma unroll
    for (int i = 0; i < IT; i++) {
        const int f   = tid + i * NTH;
        const int row = f / C4;
        const int c4  = f - row * C4;
        r[i] = *reinterpret_cast<const float4*>(Wg + row * KDIM + c4 * 4);
    }
}
template <int KDIM>
__device__ __forceinline__ void sts_w(const float4* r, float* __restrict__ Ws, int tid) {
    constexpr int C4 = KDIM / 4;
    constexpr int IT = (HID * C4) / NTH;
#pragma unroll
    for (int i = 0; i < IT; i++) {
        const int f   = tid + i * NTH;
        const int row = f / C4;
        const int c4  = f - row * C4;
        uint4 u;
        u.x = cvt_tf32(r[i].x); u.y = cvt_tf32(r[i].y);
        u.z = cvt_tf32(r[i].z); u.w = cvt_tf32(r[i].w);
        *reinterpret_cast<uint4*>(Ws + row * WPF + c4 * 4) = u;
    }
}

// C[64][128] = epi( A[64][KDIM] @ Ws^T + bg ), tf32 mma.sync. Weights are already
// staged in Ws (tf32 bits). Opens with a barrier (covers caller's sts_w + prior
// epilogue writes to A); closes mainloop with a barrier; epilogue unsynced.
template <int KDIM>
__device__ __forceinline__ void gemm_core(
    const float* __restrict__ A, const float* __restrict__ bg, float* __restrict__ C,
    const float* __restrict__ T, const float* __restrict__ R,
    const float* __restrict__ Ws, int tid, int mode)
{
    const int lane = tid & 31;
    const int wrp  = tid >> 5;
    const int g    = lane >> 2;
    const int tg   = lane & 3;
    const int mi   = wrp & 3;
    const int ni   = wrp >> 2;
    const int r0   = mi * 16 + g;
    const int r1   = r0 + 8;

    float d[4][4];
#pragma unroll
    for (int nt = 0; nt < 4; nt++) {
        const float2 b2 = *reinterpret_cast<const float2*>(bg + ni * 32 + nt * 8 + 2 * tg);
        d[nt][0] = b2.x; d[nt][1] = b2.y;
        d[nt][2] = b2.x; d[nt][3] = b2.y;
    }

    __syncthreads();   // Ws staged by all; prior writes to A visible

#pragma unroll 4
    for (int ks = 0; ks < KDIM / 8; ks++) {
        const int kk = ks * 8;
        const unsigned a0 = cvt_tf32(A[r0 * AP + kk + tg]);
        const unsigned a1 = cvt_tf32(A[r1 * AP + kk + tg]);
        const unsigned a2 = cvt_tf32(A[r0 * AP + kk + tg + 4]);
        const unsigned a3 = cvt_tf32(A[r1 * AP + kk + tg + 4]);
#pragma unroll
        for (int nt = 0; nt < 4; nt++) {
            const int n = ni * 32 + nt * 8 + g;
            const unsigned b0 = __float_as_uint(Ws[n * WPF + kk + tg]);
            const unsigned b1 = __float_as_uint(Ws[n * WPF + kk + tg + 4]);
            mma8(d[nt][0], d[nt][1], d[nt][2], d[nt][3], a0, a1, a2, a3, b0, b1);
        }
    }
    __syncthreads();   // all Ws/A reads done -> in-place C safe; next staging safe

#pragma unroll
    for (int nt = 0; nt < 4; nt++) {
        const int j = ni * 32 + nt * 8 + 2 * tg;
        float v0 = d[nt][0], v1 = d[nt][1];
        float v2 = d[nt][2], v3 = d[nt][3];
        if (mode == EPI_RELU) {
            v0 = fmaxf(v0, 0.f); v1 = fmaxf(v1, 0.f);
            v2 = fmaxf(v2, 0.f); v3 = fmaxf(v3, 0.f);
        } else if (mode == EPI_SIGADD) {
            v0 += T[r0 * AP + j]; v1 += T[r0 * AP + j + 1];
            v2 += T[r1 * AP + j]; v3 += T[r1 * AP + j + 1];
            v0 = 1.f / (1.f + __expf(-v0)); v1 = 1.f / (1.f + __expf(-v1));
            v2 = 1.f / (1.f + __expf(-v2)); v3 = 1.f / (1.f + __expf(-v3));
        } else if (mode == EPI_TANHN) {
            v0 = tanhf(T[r0 * AP + j]     + R[r0 * AP + j]     * v0);
            v1 = tanhf(T[r0 * AP + j + 1] + R[r0 * AP + j + 1] * v1);
            v2 = tanhf(T[r1 * AP + j]     + R[r1 * AP + j]     * v2);
            v3 = tanhf(T[r1 * AP + j + 1] + R[r1 * AP + j + 1] * v3);
        }
        *reinterpret_cast<float2*>(C + r0 * AP + j) = make_float2(v0, v1);
        *reinterpret_cast<float2*>(C + r1 * AP + j) = make_float2(v2, v3);
    }
    // no trailing sync
}

// Masked MHA core on tf32 mma (R12 version). Opens and closes with barriers.
__device__ __noinline__ void attention_mma(
    const float* __restrict__ Q, const float* __restrict__ K,
    const float* __restrict__ V, float* __restrict__ O,
    float* __restrict__ Ss, const u64* __restrict__ mb, int tid)
{
    const float scale = 0.17677669529663687f;  // 1/sqrt(32)
    const int lane = tid & 31;
    const int wrp  = tid >> 5;
    const int g    = lane >> 2;
    const int tg   = lane & 3;
    const int mi   = wrp & 3;
    const int r0   = mi * 16 + g;
    const int r1   = r0 + 8;
    __syncthreads();   // Q/K/V epilogue writes visible
#pragma unroll 1
    for (int h = 0; h < 4; h++) {
        const int c0 = h * 32;
        {
            const int nj = wrp >> 2;             // 2 n8-tiles at nj*16
            float sd[2][4] = {{0.f,0.f,0.f,0.f},{0.f,0.f,0.f,0.f}};
#pragma unroll
            for (int ks = 0; ks < 4; ks++) {
                const int kk = c0 + ks * 8;
                const unsigned a0 = cvt_tf32(Q[r0 * AP + kk + tg]);
                const unsigned a1 = cvt_tf32(Q[r1 * AP + kk + tg]);
                const unsigned a2 = cvt_tf32(Q[r0 * AP + kk + tg + 4]);
                const unsigned a3 = cvt_tf32(Q[r1 * AP + kk + tg + 4]);
#pragma unroll
                for (int u = 0; u < 2; u++) {
                    const int n0 = nj * 16 + u * 8;
                    const unsigned b0 = cvt_tf32(K[(n0 + g) * AP + kk + tg]);
                    const unsigned b1 = cvt_tf32(K[(n0 + g) * AP + kk + tg + 4]);
                    mma8(sd[u][0], sd[u][1], sd[u][2], sd[u][3], a0, a1, a2, a3, b0, b1);
                }
            }
#pragma unroll
            for (int u = 0; u < 2; u++) {
                const int n = nj * 16 + u * 8 + 2 * tg;
                Ss[r0 * SP + n]     = sd[u][0] * scale;
                Ss[r0 * SP + n + 1] = sd[u][1] * scale;
                Ss[r1 * SP + n]     = sd[u][2] * scale;
                Ss[r1 * SP + n + 1] = sd[u][3] * scale;
            }
        }
        __syncthreads();
        {
            const int t = tid >> 3;
            const int q = tid & 7;
            const u64 bits = mb[t];
            float mx = -1e30f;
            for (int m = q; m < N_ANT; m += 8)
                if ((bits >> m) & 1ULL) mx = fmaxf(mx, Ss[t * SP + m]);
            mx = fmaxf(mx, __shfl_xor_sync(0xffffffffu, mx, 1));
            mx = fmaxf(mx, __shfl_xor_sync(0xffffffffu, mx, 2));
            mx = fmaxf(mx, __shfl_xor_sync(0xffffffffu, mx, 4));
            float sum = 0.f;
            for (int m = q; m < N_ANT; m += 8) {
                const float p = ((bits >> m) & 1ULL) ? __expf(Ss[t * SP + m] - mx) : 0.f;
                Ss[t * SP + m] = p;
                sum += p;
            }
            sum += __shfl_xor_sync(0xffffffffu, sum, 1);
            sum += __shfl_xor_sync(0xffffffffu, sum, 2);
            sum += __shfl_xor_sync(0xffffffffu, sum, 4);
            const float rinv = 1.f / sum;
            for (int m = q; m < N_ANT; m += 8) Ss[t * SP + m] *= rinv;
        }
        __syncthreads();
        {
            const int nt = wrp >> 2;             // 1 n8-tile per warp
            float od[4] = {0.f, 0.f, 0.f, 0.f};
#pragma unroll
            for (int ks = 0; ks < 8; ks++) {
                const int kk = ks * 8;
                const unsigned a0 = cvt_tf32(Ss[r0 * SP + kk + tg]);
                const unsigned a1 = cvt_tf32(Ss[r1 * SP + kk + tg]);
                const unsigned a2 = cvt_tf32(Ss[r0 * SP + kk + tg + 4]);
                const unsigned a3 = cvt_tf32(Ss[r1 * SP + kk + tg + 4]);
                const unsigned b0 = cvt_tf32(V[(kk + tg) * AP + c0 + nt * 8 + g]);
                const unsigned b1 = cvt_tf32(V[(kk + tg + 4) * AP + c0 + nt * 8 + g]);
                mma8(od[0], od[1], od[2], od[3], a0, a1, a2, a3, b0, b1);
            }
            const int j = c0 + nt * 8 + 2 * tg;
            *reinterpret_cast<float2*>(O + r0 * AP + j) = make_float2(od[0], od[1]);
            *reinterpret_cast<float2*>(O + r1 * AP + j) = make_float2(od[2], od[3]);
        }
        __syncthreads();
    }
}

__global__ void __launch_bounds__(NTH, 1) drgn_kernel(
    const float* __restrict__ x, const int* __restrict__ mask,
    const float* __restrict__ hs,
    const float* __restrict__ enc_w, const float* __restrict__ enc_b,
    const float* __restrict__ q1_w, const float* __restrict__ q1_b,
    const float* __restrict__ k1_w, const float* __restrict__ k1_b,
    const float* __restrict__ v1_w, const float* __restrict__ v1_b,
    const float* __restrict__ o1_w, const float* __restrict__ o1_b,
    const float* __restrict__ q2_w, const float* __restrict__ q2_b,
    const float* __restrict__ k2_w, const float* __restrict__ k2_b,
    const float* __restrict__ v2_w, const float* __restrict__ v2_b,
    const float* __restrict__ o2_w, const float* __restrict__ o2_b,
    const float* __restrict__ w_ih, const float* __restrict__ w_hh,
    const float* __restrict__ b_ih, const float* __restrict__ b_hh,
    const float* __restrict__ lin_w, const float* __restrict__ lin_b,
    float* __restrict__ qs_out, float* __restrict__ h3_out, int act)
{
    extern __shared__ char smem_raw[];
    SmemLayout* s = reinterpret_cast<SmemLayout*>(smem_raw);
    const int tid = threadIdx.x;
    const int b   = blockIdx.x;

    float4 wreg[8];                       // register-resident weight prefetch buffer
    ldg_w<64>(enc_w, tid, wreg);          // enc weights fly during x/mask load

    // ---- load x tile and mask bitmap (parallel bitmap: 8 thr/row, int4 loads) ----
    {
        const float* xb = x + (size_t)b * (N_ANT * 64);
        for (int idx = tid; idx < N_ANT * 64; idx += NTH)
            s->B0[(idx >> 6) * AP + (idx & 63)] = xb[idx];

        const int row = tid >> 3;      // 0..63
        const int oq  = tid & 7;       // octet of 8 mask ints
        const int4* mrow = reinterpret_cast<const int4*>(
            mask + ((size_t)b * N_ANT + row) * N_ANT + oq * 8);
        const int4 m0 = mrow[0];
        const int4 m1 = mrow[1];
        unsigned byte =
            (unsigned)(m0.x != 0)        | ((unsigned)(m0.y != 0) << 1) |
            ((unsigned)(m0.z != 0) << 2) | ((unsigned)(m0.w != 0) << 3) |
            ((unsigned)(m1.x != 0) << 4) | ((unsigned)(m1.y != 0) << 5) |
            ((unsigned)(m1.z != 0) << 6) | ((unsigned)(m1.w != 0) << 7);
        u64 part = (u64)byte << (8 * oq);
        part |= __shfl_xor_sync(0xffffffffu, part, 1);
        part |= __shfl_xor_sync(0xffffffffu, part, 2);
        part |= __shfl_xor_sync(0xffffffffu, part, 4);
        if (oq == 0) s->mb[row] = part;
    }

    // ---- encoder: xe = relu(x @ enc_w^T) -> B1 ----
    sts_w<64>(wreg, s->Ws, tid);  ldg_w<128>(q1_w, tid, wreg);
    gemm_core<64>(s->B0, enc_b, s->B1, nullptr, nullptr, s->Ws, tid, EPI_RELU);

    // ---- MHA layer 1 (input xe in B1) ----
    sts_w<128>(wreg, s->Ws, tid); ldg_w<128>(k1_w, tid, wreg);
    gemm_core<128>(s->B1, q1_b, s->B0, nullptr, nullptr, s->Ws, tid, EPI_RELU);
    sts_w<128>(wreg, s->Ws, tid); ldg_w<128>(v1_w, tid, wreg);
    gemm_core<128>(s->B1, k1_b, s->B2, nullptr, nullptr, s->Ws, tid, EPI_RELU);
    sts_w<128>(wreg, s->Ws, tid);                         // no prefetch across attention
    gemm_core<128>(s->B1, v1_b, s->B3, nullptr, nullptr, s->Ws, tid, EPI_RELU);
    attention_mma(s->B0, s->B2, s->B3, s->B1, s->Ss, s->mb, tid);
    ldg_w<128>(o1_w, tid, wreg);                          // exposed (1 of 2)
    sts_w<128>(wreg, s->Ws, tid); ldg_w<128>(q2_w, tid, wreg);
    gemm_core<128>(s->B1, o1_b, s->B0, nullptr, nullptr, s->Ws, tid, EPI_RELU);  // h1 -> B0

    // ---- MHA layer 2 (input h1 in B0) ----
    sts_w<128>(wreg, s->Ws, tid); ldg_w<128>(k2_w, tid, wreg);
    gemm_core<128>(s->B0, q2_b, s->B1, nullptr, nullptr, s->Ws, tid, EPI_RELU);
    sts_w<128>(wreg, s->Ws, tid); ldg_w<128>(v2_w, tid, wreg);
    gemm_core<128>(s->B0, k2_b, s->B2, nullptr, nullptr, s->Ws, tid, EPI_RELU);
    sts_w<128>(wreg, s->Ws, tid);                         // no prefetch across attention
    gemm_core<128>(s->B0, v2_b, s->B3, nullptr, nullptr, s->Ws, tid, EPI_RELU);
    attention_mma(s->B1, s->B2, s->B3, s->B0, s->Ss, s->mb, tid);
    ldg_w<128>(o2_w, tid, wreg);                          // exposed (2 of 2)
    sts_w<128>(wreg, s->Ws, tid); ldg_w<128>(w_ih, tid, wreg);
    gemm_core<128>(s->B0, o2_b, s->B1, nullptr, nullptr, s->Ws, tid, EPI_RELU);  // h2 -> B1

    // ---- load previous hidden state -> B2 ----
    {
        const float* hb = hs + (size_t)b * (N_ANT * HID);
        for (int idx = tid; idx < N_ANT * HID; idx += NTH)
            s->B2[(idx >> 7) * AP + (idx & 127)] = hb[idx];
    }

    // ---- GRU cell: h2 (B1), h (B2) ----
    sts_w<128>(wreg, s->Ws, tid); ldg_w<128>(w_ih + 128 * HID, tid, wreg);
    gemm_core<128>(s->B1, b_ih,       s->B0, nullptr, nullptr, s->Ws, tid, EPI_PLAIN);   // i_r
    sts_w<128>(wreg, s->Ws, tid); ldg_w<128>(w_ih + 256 * HID, tid, wreg);
    gemm_core<128>(s->B1, b_ih + 128, s->B3, nullptr, nullptr, s->Ws, tid, EPI_PLAIN);   // i_z
    sts_w<128>(wreg, s->Ws, tid); ldg_w<128>(w_hh, tid, wreg);
    gemm_core<128>(s->B1, b_ih + 256, s->B1, nullptr, nullptr, s->Ws, tid, EPI_PLAIN);   // i_n (in place)
    sts_w<128>(wreg, s->Ws, tid); ldg_w<128>(w_hh + 128 * HID, tid, wreg);
    gemm_core<128>(s->B2, b_hh,       s->B0, s->B0, nullptr, s->Ws, tid, EPI_SIGADD);    // r
    sts_w<128>(wreg, s->Ws, tid); ldg_w<128>(w_hh + 256 * HID, tid, wreg);
    gemm_core<128>(s->B2, b_hh + 128, s->B3, s->B3, nullptr, s->Ws, tid, EPI_SIGADD);    // z
    sts_w<128>(wreg, s->Ws, tid);
    gemm_core<128>(s->B2, b_hh + 256, s->B1, s->B1, s->B0, s->Ws, tid, EPI_TANHN);       // n

    __syncthreads();   // z/n epilogue writes visible before the combine

    // ---- h3 = (1-z)*n + z*h ; write h3 to gmem and keep in B1 ----
    {
        float* h3b = h3_out + (size_t)b * (N_ANT * HID);
        for (int idx = tid; idx < N_ANT * HID; idx += NTH) {
            const int off = (idx >> 7) * AP + (idx & 127);
            const float z  = s->B3[off];
            const float h3 = (1.f - z) * s->B1[off] + z * s->B2[off];
            s->B1[off] = h3;
            h3b[idx]   = h3;
        }
    }
    __syncthreads();

    // ---- qs = h3 @ lin_w^T + lin_b ----
    {
        float* qb = qs_out + (size_t)b * (N_ANT * act);
        for (int idx = tid; idx < N_ANT * act; idx += NTH) {
            const int t = idx / act;
            const int a = idx - t * act;
            const float* wr = lin_w + a * HID;
            const float* hr = s->B1 + t * AP;
            float sacc = lin_b[a];
#pragma unroll 8
            for (int k = 0; k < HID; k += 4) {
                const float4 h4 = *reinterpret_cast<const float4*>(hr + k);
                const float4 w4 = *reinterpret_cast<const float4*>(wr + k);
                sacc = fmaf(h4.x, w4.x, sacc);
                sacc = fmaf(h4.y, w4.y, sacc);
                sacc = fmaf(h4.z, w4.z, sacc);
                sacc = fmaf(h4.w, w4.w, sacc);
            }
            qb[idx] = sacc;
        }
    }
}

extern "C" void kernel_launch(void* const* d_in, const int* in_sizes, int n_in,
                              void* d_out, int out_size)
{
    const float* x     = (const float*)d_in[0];
    const int*   mask  = (const int*)  d_in[1];
    const float* hs    = (const float*)d_in[2];
    const float* enc_w = (const float*)d_in[3];
    const float* enc_b = (const float*)d_in[4];
    const float* q1_w  = (const float*)d_in[5];
    const float* q1_b  = (const float*)d_in[6];
    const float* k1_w  = (const float*)d_in[7];
    const float* k1_b  = (const float*)d_in[8];
    const float* v1_w  = (const float*)d_in[9];
    const float* v1_b  = (const float*)d_in[10];
    const float* o1_w  = (const float*)d_in[11];
    const float* o1_b  = (const float*)d_in[12];
    const float* q2_w  = (const float*)d_in[13];
    const float* q2_b  = (const float*)d_in[14];
    const float* k2_w  = (const float*)d_in[15];
    const float* k2_b  = (const float*)d_in[16];
    const float* v2_w  = (const float*)d_in[17];
    const float* v2_b  = (const float*)d_in[18];
    const float* o2_w  = (const float*)d_in[19];
    const float* o2_b  = (const float*)d_in[20];
    const float* w_ih  = (const float*)d_in[21];
    const float* w_hh  = (const float*)d_in[22];
    const float* b_ih  = (const float*)d_in[23];
    const float* b_hh  = (const float*)d_in[24];
    const float* lin_w = (const float*)d_in[25];
    const float* lin_b = (const float*)d_in[26];

    const int bs  = in_sizes[0] / (N_ANT * 64);
    const int act = in_sizes[25] / HID;  // 20

    float* qs = (float*)d_out;
    float* h3 = qs + (size_t)bs * N_ANT * act;

    const int smem_bytes = (int)sizeof(SmemLayout);
    cudaFuncSetAttribute(drgn_kernel, cudaFuncAttributeMaxDynamicSharedMemorySize, smem_bytes);

    drgn_kernel<<<bs, NTH, smem_bytes>>>(
        x, mask, hs, enc_w, enc_b,
        q1_w, q1_b, k1_w, k1_b, v1_w, v1_b, o1_w, o1_b,
        q2_w, q2_b, k2_w, k2_b, v2_w, v2_b, o2_w, o2_b,
        w_ih, w_hh, b_ih, b_hh, lin_w, lin_b,
        qs, h3, act);
}

// round 15
// speedup vs baseline: 1.4604x; 1.0373x over previous
#include <cuda_runtime.h>
#include <math.h>

#define N_ANT 64
#define HID   128
#define AP    132   // activation pitch: (4g+tg) bank map -> A-fragment LDS conflict-free
#define WPF   132   // full-weight pitch: B-fragment loads conflict-free
#define SPH   66    // per-head score pitch (4 planes alias Ws exactly)
#define NTH   512

typedef unsigned long long u64;

__device__ __forceinline__ unsigned cvt_tf32(float v) {
    unsigned r; asm("cvt.rna.tf32.f32 %0, %1;" : "=r"(r) : "f"(v)); return r;
}
__device__ __forceinline__ void mma8(float& d0, float& d1, float& d2, float& d3,
                                     unsigned a0, unsigned a1, unsigned a2, unsigned a3,
                                     unsigned b0, unsigned b1) {
    asm("mma.sync.aligned.m16n8k8.row.col.f32.tf32.tf32.f32 "
        "{%0,%1,%2,%3},{%4,%5,%6,%7},{%8,%9},{%0,%1,%2,%3};"
        : "+f"(d0), "+f"(d1), "+f"(d2), "+f"(d3)
        : "r"(a0), "r"(a1), "r"(a2), "r"(a3), "r"(b0), "r"(b1));
}

struct __align__(16) SmemLayout {
    float B0[N_ANT * AP];
    float B1[N_ANT * AP];
    float B2[N_ANT * AP];
    float B3[N_ANT * AP];
    union {
        float Ws[HID * WPF];            // 16896 floats: one staged weight matrix
        float Ss[4 * N_ANT * SPH];      // 16896 floats: 4 head score planes
    };
    u64   mb[N_ANT];
};

#define EPI_PLAIN  0
#define EPI_RELU   1
#define EPI_SIGADD 2   // C = sigmoid(acc + T)
#define EPI_TANHN  3   // C = tanh(T + R*acc)

// ---- weight movement: coalesced LDG into registers / tf32-rounded STS ----
template <int KDIM>
__device__ __forceinline__ void ldg_w(const float* __restrict__ Wg, int tid, float4* r) {
    constexpr int C4 = KDIM / 4;
    constexpr int IT = (HID * C4) / NTH;   // 8 (K=128) or 4 (K=64)
#pragma unroll
    for (int i = 0; i < IT; i++) {
        const int f   = tid + i * NTH;
        const int row = f / C4;
        const int c4  = f - row * C4;
        r[i] = *reinterpret_cast<const float4*>(Wg + row * KDIM + c4 * 4);
    }
}
template <int KDIM>
__device__ __forceinline__ void sts_w(const float4* r, float* __restrict__ Ws, int tid) {
    constexpr int C4 = KDIM / 4;
    constexpr int IT = (HID * C4) / NTH;
#pragma unroll
    for (int i = 0; i < IT; i++) {
        const int f   = tid + i * NTH;
        const int row = f / C4;
        const int c4  = f - row * C4;
        uint4 u;
        u.x = cvt_tf32(r[i].x); u.y = cvt_tf32(r[i].y);
        u.z = cvt_tf32(r[i].z); u.w = cvt_tf32(r[i].w);
        *reinterpret_cast<uint4*>(Ws + row * WPF + c4 * 4) = u;
    }
}

// C[64][128] = epi( A[64][KDIM] @ Ws^T + bg ), tf32 mma.sync. Weights pre-staged.
// Opens with a barrier (covers caller's sts_w + prior writes to A); closes the
// mainloop with a barrier; epilogue unsynced.
template <int KDIM>
__device__ __forceinline__ void gemm_core(
    const float* __restrict__ A, const float* __restrict__ bg, float* __restrict__ C,
    const float* __restrict__ T, const float* __restrict__ R,
    const float* __restrict__ Ws, int tid, int mode)
{
    const int lane = tid & 31;
    const int wrp  = tid >> 5;
    const int g    = lane >> 2;
    const int tg   = lane & 3;
    const int mi   = wrp & 3;
    const int ni   = wrp >> 2;
    const int r0   = mi * 16 + g;
    const int r1   = r0 + 8;

    float d[4][4];
#pragma unroll
    for (int nt = 0; nt < 4; nt++) {
        const float2 b2 = *reinterpret_cast<const float2*>(bg + ni * 32 + nt * 8 + 2 * tg);
        d[nt][0] = b2.x; d[nt][1] = b2.y;
        d[nt][2] = b2.x; d[nt][3] = b2.y;
    }

    __syncthreads();   // Ws staged by all; prior writes to A visible

#pragma unroll 4
    for (int ks = 0; ks < KDIM / 8; ks++) {
        const int kk = ks * 8;
        const unsigned a0 = cvt_tf32(A[r0 * AP + kk + tg]);
        const unsigned a1 = cvt_tf32(A[r1 * AP + kk + tg]);
        const unsigned a2 = cvt_tf32(A[r0 * AP + kk + tg + 4]);
        const unsigned a3 = cvt_tf32(A[r1 * AP + kk + tg + 4]);
#pragma unroll
        for (int nt = 0; nt < 4; nt++) {
            const int n = ni * 32 + nt * 8 + g;
            const unsigned b0 = __float_as_uint(Ws[n * WPF + kk + tg]);
            const unsigned b1 = __float_as_uint(Ws[n * WPF + kk + tg + 4]);
            mma8(d[nt][0], d[nt][1], d[nt][2], d[nt][3], a0, a1, a2, a3, b0, b1);
        }
    }
    __syncthreads();   // all Ws/A reads done -> in-place C safe; next staging safe

#pragma unroll
    for (int nt = 0; nt < 4; nt++) {
        const int j = ni * 32 + nt * 8 + 2 * tg;
        float v0 = d[nt][0], v1 = d[nt][1];
        float v2 = d[nt][2], v3 = d[nt][3];
        if (mode == EPI_RELU) {
            v0 = fmaxf(v0, 0.f); v1 = fmaxf(v1, 0.f);
            v2 = fmaxf(v2, 0.f); v3 = fmaxf(v3, 0.f);
        } else if (mode == EPI_SIGADD) {
            v0 += T[r0 * AP + j]; v1 += T[r0 * AP + j + 1];
            v2 += T[r1 * AP + j]; v3 += T[r1 * AP + j + 1];
            v0 = 1.f / (1.f + __expf(-v0)); v1 = 1.f / (1.f + __expf(-v1));
            v2 = 1.f / (1.f + __expf(-v2)); v3 = 1.f / (1.f + __expf(-v3));
        } else if (mode == EPI_TANHN) {
            v0 = tanhf(T[r0 * AP + j]     + R[r0 * AP + j]     * v0);
            v1 = tanhf(T[r0 * AP + j + 1] + R[r0 * AP + j + 1] * v1);
            v2 = tanhf(T[r1 * AP + j]     + R[r1 * AP + j]     * v2);
            v3 = tanhf(T[r1 * AP + j + 1] + R[r1 * AP + j + 1] * v3);
        }
        *reinterpret_cast<float2*>(C + r0 * AP + j) = make_float2(v0, v1);
        *reinterpret_cast<float2*>(C + r1 * AP + j) = make_float2(v2, v3);
    }
    // no trailing sync
}

// Head-parallel masked MHA: all 4 heads in one scores / one softmax / one AV phase.
// Warp (mi = wrp&3, h = wrp>>2). Ss = 4 planes of [64][SPH] (aliases Ws).
__device__ __noinline__ void attention_mma(
    const float* __restrict__ Q, const float* __restrict__ K,
    const float* __restrict__ V, float* __restrict__ O,
    float* __restrict__ Ss, const u64* __restrict__ mb, int tid)
{
    const float scale = 0.17677669529663687f;  // 1/sqrt(32)
    const int lane = tid & 31;
    const int wrp  = tid >> 5;
    const int g    = lane >> 2;
    const int tg   = lane & 3;
    const int mi   = wrp & 3;
    const int h    = wrp >> 2;
    const int c0   = h * 32;
    const int r0   = mi * 16 + g;
    const int r1   = r0 + 8;
    float* SsH = Ss + h * (N_ANT * SPH);

    __syncthreads();   // Q/K/V epilogue writes visible; Ws (= Ss alias) fully consumed

    // ---- scores: warp computes 16x64 band of S_h = scale * Q_h @ K_h^T ----
    {
        float sd[8][4];
#pragma unroll
        for (int nt = 0; nt < 8; nt++) { sd[nt][0] = sd[nt][1] = sd[nt][2] = sd[nt][3] = 0.f; }
#pragma unroll
        for (int ks = 0; ks < 4; ks++) {
            const int kk = c0 + ks * 8;
            const unsigned a0 = cvt_tf32(Q[r0 * AP + kk + tg]);
            const unsigned a1 = cvt_tf32(Q[r1 * AP + kk + tg]);
            const unsigned a2 = cvt_tf32(Q[r0 * AP + kk + tg + 4]);
            const unsigned a3 = cvt_tf32(Q[r1 * AP + kk + tg + 4]);
#pragma unroll
            for (int nt = 0; nt < 8; nt++) {
                const unsigned b0 = cvt_tf32(K[(nt * 8 + g) * AP + kk + tg]);
                const unsigned b1 = cvt_tf32(K[(nt * 8 + g) * AP + kk + tg + 4]);
                mma8(sd[nt][0], sd[nt][1], sd[nt][2], sd[nt][3], a0, a1, a2, a3, b0, b1);
            }
        }
#pragma unroll
        for (int nt = 0; nt < 8; nt++) {
            const int j = nt * 8 + 2 * tg;
            *reinterpret_cast<float2*>(SsH + r0 * SPH + j) =
                make_float2(sd[nt][0] * scale, sd[nt][1] * scale);
            *reinterpret_cast<float2*>(SsH + r1 * SPH + j) =
                make_float2(sd[nt][2] * scale, sd[nt][3] * scale);
        }
    }
    __syncthreads();

    // ---- masked softmax: 2 threads per (row, head) pair ----
    {
        const int pairIdx = tid >> 1;        // 0..255
        const int q  = tid & 1;
        const int t  = pairIdx & 63;
        const int hh = pairIdx >> 6;
        float* P = Ss + hh * (N_ANT * SPH) + t * SPH;
        const u64 bits = mb[t];
        float mx = -1e30f;
        for (int m = q; m < N_ANT; m += 2)
            if ((bits >> m) & 1ULL) mx = fmaxf(mx, P[m]);
        mx = fmaxf(mx, __shfl_xor_sync(0xffffffffu, mx, 1));
        float sum = 0.f;
        for (int m = q; m < N_ANT; m += 2) {
            const float p = ((bits >> m) & 1ULL) ? __expf(P[m] - mx) : 0.f;
            P[m] = p;
            sum += p;
        }
        sum += __shfl_xor_sync(0xffffffffu, sum, 1);
        const float rinv = 1.f / sum;
        for (int m = q; m < N_ANT; m += 2) P[m] *= rinv;
    }
    __syncthreads();

    // ---- AV: warp computes 16x32 band of O[:, c0:c0+32] = P_h @ V[:, c0:c0+32] ----
    {
        float od[4][4];
#pragma unroll
        for (int nt = 0; nt < 4; nt++) { od[nt][0] = od[nt][1] = od[nt][2] = od[nt][3] = 0.f; }
#pragma unroll
        for (int ks = 0; ks < 8; ks++) {
            const int kk = ks * 8;
            const unsigned a0 = cvt_tf32(SsH[r0 * SPH + kk + tg]);
            const unsigned a1 = cvt_tf32(SsH[r1 * SPH + kk + tg]);
            const unsigned a2 = cvt_tf32(SsH[r0 * SPH + kk + tg + 4]);
            const unsigned a3 = cvt_tf32(SsH[r1 * SPH + kk + tg + 4]);
#pragma unroll
            for (int nt = 0; nt < 4; nt++) {
                const unsigned b0 = cvt_tf32(V[(kk + tg) * AP + c0 + nt * 8 + g]);
                const unsigned b1 = cvt_tf32(V[(kk + tg + 4) * AP + c0 + nt * 8 + g]);
                mma8(od[nt][0], od[nt][1], od[nt][2], od[nt][3], a0, a1, a2, a3, b0, b1);
            }
        }
#pragma unroll
        for (int nt = 0; nt < 4; nt++) {
            const int j = c0 + nt * 8 + 2 * tg;
            *reinterpret_cast<float2*>(O + r0 * AP + j) = make_float2(od[nt][0], od[nt][1]);
            *reinterpret_cast<float2*>(O + r1 * AP + j) = make_float2(od[nt][2], od[nt][3]);
        }
    }
    __syncthreads();   // scores plane (Ws alias) free for next sts_w; O visible
}

__global__ void __launch_bounds__(NTH, 1) drgn_kernel(
    const float* __restrict__ x, const int* __restrict__ mask,
    const float* __restrict__ hs,
    const float* __restrict__ enc_w, const float* __restrict__ enc_b,
    const float* __restrict__ q1_w, const float* __restrict__ q1_b,
    const float* __restrict__ k1_w, const float* __restrict__ k1_b,
    const float* __restrict__ v1_w, const float* __restrict__ v1_b,
    const float* __restrict__ o1_w, const float* __restrict__ o1_b,
    const float* __restrict__ q2_w, const float* __restrict__ q2_b,
    const float* __restrict__ k2_w, const float* __restrict__ k2_b,
    const float* __restrict__ v2_w, const float* __restrict__ v2_b,
    const float* __restrict__ o2_w, const float* __restrict__ o2_b,
    const float* __restrict__ w_ih, const float* __restrict__ w_hh,
    const float* __restrict__ b_ih, const float* __restrict__ b_hh,
    const float* __restrict__ lin_w, const float* __restrict__ lin_b,
    float* __restrict__ qs_out, float* __restrict__ h3_out, int act)
{
    extern __shared__ char smem_raw[];
    SmemLayout* s = reinterpret_cast<SmemLayout*>(smem_raw);
    const int tid = threadIdx.x;
    const int b   = blockIdx.x;

    float4 wreg[8];                       // register-resident weight prefetch buffer
    ldg_w<64>(enc_w, tid, wreg);          // enc weights fly during x/mask load

    // ---- load x tile and mask bitmap (parallel bitmap: 8 thr/row, int4 loads) ----
    {
        const float* xb = x + (size_t)b * (N_ANT * 64);
        for (int idx = tid; idx < N_ANT * 64; idx += NTH)
            s->B0[(idx >> 6) * AP + (idx & 63)] = xb[idx];

        const int row = tid >> 3;      // 0..63
        const int oq  = tid & 7;       // octet of 8 mask ints
        const int4* mrow = reinterpret_cast<const int4*>(
            mask + ((size_t)b * N_ANT + row) * N_ANT + oq * 8);
        const int4 m0 = mrow[0];
        const int4 m1 = mrow[1];
        unsigned byte =
            (unsigned)(m0.x != 0)        | ((unsigned)(m0.y != 0) << 1) |
            ((unsigned)(m0.z != 0) << 2) | ((unsigned)(m0.w != 0) << 3) |
            ((unsigned)(m1.x != 0) << 4) | ((unsigned)(m1.y != 0) << 5) |
            ((unsigned)(m1.z != 0) << 6) | ((unsigned)(m1.w != 0) << 7);
        u64 part = (u64)byte << (8 * oq);
        part |= __shfl_xor_sync(0xffffffffu, part, 1);
        part |= __shfl_xor_sync(0xffffffffu, part, 2);
        part |= __shfl_xor_sync(0xffffffffu, part, 4);
        if (oq == 0) s->mb[row] = part;
    }

    // ---- encoder: xe = relu(x @ enc_w^T) -> B1 ----
    sts_w<64>(wreg, s->Ws, tid);  ldg_w<128>(q1_w, tid, wreg);
    gemm_core<64>(s->B0, enc_b, s->B1, nullptr, nullptr, s->Ws, tid, EPI_RELU);

    // ---- MHA layer 1 (input xe in B1) ----
    sts_w<128>(wreg, s->Ws, tid); ldg_w<128>(k1_w, tid, wreg);
    gemm_core<128>(s->B1, q1_b, s->B0, nullptr, nullptr, s->Ws, tid, EPI_RELU);
    sts_w<128>(wreg, s->Ws, tid); ldg_w<128>(v1_w, tid, wreg);
    gemm_core<128>(s->B1, k1_b, s->B2, nullptr, nullptr, s->Ws, tid, EPI_RELU);
    sts_w<128>(wreg, s->Ws, tid);                         // no prefetch across attention
    gemm_core<128>(s->B1, v1_b, s->B3, nullptr, nullptr, s->Ws, tid, EPI_RELU);
    attention_mma(s->B0, s->B2, s->B3, s->B1, s->Ss, s->mb, tid);
    ldg_w<128>(o1_w, tid, wreg);                          // exposed (1 of 2)
    sts_w<128>(wreg, s->Ws, tid); ldg_w<128>(q2_w, tid, wreg);
    gemm_core<128>(s->B1, o1_b, s->B0, nullptr, nullptr, s->Ws, tid, EPI_RELU);  // h1 -> B0

    // ---- MHA layer 2 (input h1 in B0) ----
    sts_w<128>(wreg, s->Ws, tid); ldg_w<128>(k2_w, tid, wreg);
    gemm_core<128>(s->B0, q2_b, s->B1, nullptr, nullptr, s->Ws, tid, EPI_RELU);
    sts_w<128>(wreg, s->Ws, tid); ldg_w<128>(v2_w, tid, wreg);
    gemm_core<128>(s->B0, k2_b, s->B2, nullptr, nullptr, s->Ws, tid, EPI_RELU);
    sts_w<128>(wreg, s->Ws, tid);                         // no prefetch across attention
    gemm_core<128>(s->B0, v2_b, s->B3, nullptr, nullptr, s->Ws, tid, EPI_RELU);
    attention_mma(s->B1, s->B2, s->B3, s->B0, s->Ss, s->mb, tid);
    ldg_w<128>(o2_w, tid, wreg);                          // exposed (2 of 2)
    sts_w<128>(wreg, s->Ws, tid); ldg_w<128>(w_ih, tid, wreg);
    gemm_core<128>(s->B0, o2_b, s->B1, nullptr, nullptr, s->Ws, tid, EPI_RELU);  // h2 -> B1

    // ---- load previous hidden state -> B2 ----
    {
        const float* hb = hs + (size_t)b * (N_ANT * HID);
        for (int idx = tid; idx < N_ANT * HID; idx += NTH)
            s->B2[(idx >> 7) * AP + (idx & 127)] = hb[idx];
    }

    // ---- GRU cell: h2 (B1), h (B2) ----
    sts_w<128>(wreg, s->Ws, tid); ldg_w<128>(w_ih + 128 * HID, tid, wreg);
    gemm_core<128>(s->B1, b_ih,       s->B0, nullptr, nullptr, s->Ws, tid, EPI_PLAIN);   // i_r
    sts_w<128>(wreg, s->Ws, tid); ldg_w<128>(w_ih + 256 * HID, tid, wreg);
    gemm_core<128>(s->B1, b_ih + 128, s->B3, nullptr, nullptr, s->Ws, tid, EPI_PLAIN);   // i_z
    sts_w<128>(wreg, s->Ws, tid); ldg_w<128>(w_hh, tid, wreg);
    gemm_core<128>(s->B1, b_ih + 256, s->B1, nullptr, nullptr, s->Ws, tid, EPI_PLAIN);   // i_n (in place)
    sts_w<128>(wreg, s->Ws, tid); ldg_w<128>(w_hh + 128 * HID, tid, wreg);
    gemm_core<128>(s->B2, b_hh,       s->B0, s->B0, nullptr, s->Ws, tid, EPI_SIGADD);    // r
    sts_w<128>(wreg, s->Ws, tid); ldg_w<128>(w_hh + 256 * HID, tid, wreg);
    gemm_core<128>(s->B2, b_hh + 128, s->B3, s->B3, nullptr, s->Ws, tid, EPI_SIGADD);    // z
    sts_w<128>(wreg, s->Ws, tid);
    gemm_core<128>(s->B2, b_hh + 256, s->B1, s->B1, s->B0, s->Ws, tid, EPI_TANHN);       // n

    __syncthreads();   // z/n epilogue writes visible before the combine

    // ---- h3 = (1-z)*n + z*h ; write h3 to gmem and keep in B1 ----
    {
        float* h3b = h3_out + (size_t)b * (N_ANT * HID);
        for (int idx = tid; idx < N_ANT * HID; idx += NTH) {
            const int off = (idx >> 7) * AP + (idx & 127);
            const float z  = s->B3[off];
            const float h3 = (1.f - z) * s->B1[off] + z * s->B2[off];
            s->B1[off] = h3;
            h3b[idx]   = h3;
        }
    }
    __syncthreads();

    // ---- qs = h3 @ lin_w^T + lin_b ----
    {
        float* qb = qs_out + (size_t)b * (N_ANT * act);
        for (int idx = tid; idx < N_ANT * act; idx += NTH) {
            const int t = idx / act;
            const int a = idx - t * act;
            const float* wr = lin_w + a * HID;
            const float* hr = s->B1 + t * AP;
            float sacc = lin_b[a];
#pragma unroll 8
            for (int k = 0; k < HID; k += 4) {
                const float4 h4 = *reinterpret_cast<const float4*>(hr + k);
                const float4 w4 = *reinterpret_cast<const float4*>(wr + k);
                sacc = fmaf(h4.x, w4.x, sacc);
                sacc = fmaf(h4.y, w4.y, sacc);
                sacc = fmaf(h4.z, w4.z, sacc);
                sacc = fmaf(h4.w, w4.w, sacc);
            }
            qb[idx] = sacc;
        }
    }
}

extern "C" void kernel_launch(void* const* d_in, const int* in_sizes, int n_in,
                              void* d_out, int out_size)
{
    const float* x     = (const float*)d_in[0];
    const int*   mask  = (const int*)  d_in[1];
    const float* hs    = (const float*)d_in[2];
    const float* enc_w = (const float*)d_in[3];
    const float* enc_b = (const float*)d_in[4];
    const float* q1_w  = (const float*)d_in[5];
    const float* q1_b  = (const float*)d_in[6];
    const float* k1_w  = (const float*)d_in[7];
    const float* k1_b  = (const float*)d_in[8];
    const float* v1_w  = (const float*)d_in[9];
    const float* v1_b  = (const float*)d_in[10];
    const float* o1_w  = (const float*)d_in[11];
    const float* o1_b  = (const float*)d_in[12];
    const float* q2_w  = (const float*)d_in[13];
    const float* q2_b  = (const float*)d_in[14];
    const float* k2_w  = (const float*)d_in[15];
    const float* k2_b  = (const float*)d_in[16];
    const float* v2_w  = (const float*)d_in[17];
    const float* v2_b  = (const float*)d_in[18];
    const float* o2_w  = (const float*)d_in[19];
    const float* o2_b  = (const float*)d_in[20];
    const float* w_ih  = (const float*)d_in[21];
    const float* w_hh  = (const float*)d_in[22];
    const float* b_ih  = (const float*)d_in[23];
    const float* b_hh  = (const float*)d_in[24];
    const float* lin_w = (const float*)d_in[25];
    const float* lin_b = (const float*)d_in[26];

    const int bs  = in_sizes[0] / (N_ANT * 64);
    const int act = in_sizes[25] / HID;  // 20

    float* qs = (float*)d_out;
    float* h3 = qs + (size_t)bs * N_ANT * act;

    const int smem_bytes = (int)sizeof(SmemLayout);
    cudaFuncSetAttribute(drgn_kernel, cudaFuncAttributeMaxDynamicSharedMemorySize, smem_bytes);

    drgn_kernel<<<bs, NTH, smem_bytes>>>(
        x, mask, hs, enc_w, enc_b,
        q1_w, q1_b, k1_w, k1_b, v1_w, v1_b, o1_w, o1_b,
        q2_w, q2_b, k2_w, k2_b, v2_w, v2_b, o2_w, o2_b,
        w_ih, w_hh, b_ih, b_hh, lin_w, lin_b,
        qs, h3, act);
}